// round 16
// baseline (speedup 1.0000x reference)
#include <cuda_runtime.h>
#include <cuda_bf16.h>
#include <cstdint>

#define NPROTO 64
#define PDIM   512
#define NFEAT  200000
#define EPSN   1e-8f
#define NACC   148                       // persistent CTAs (== #partial slices)
#define CHUNK  32                        // rows per staged chunk
#define NCHUNK (NFEAT / CHUNK)           // 6250, exact (no tail)

// ---------------- device scratch (static; no allocation) ----------------
// B fragments, coalesced: g_B[(nblk*32+ks)*32 + lane], lane = rg*4+q holds
// { bf16x2(Pn[16ks+2q..]), bf16x2(Pn[16ks+8+2q..]) } for proto n = nblk*8+rg.
__device__ uint2 g_B[8 * 32 * 32];
__device__ float g_Partial[NACC * NPROTO * PDIM];   // per-CTA segment sums (~19.4 MB)
__device__ int   g_Cnt[NPROTO];

__device__ __forceinline__ uint32_t smem_u32(const void* p) {
    uint32_t a;
    asm("{ .reg .u64 t; cvta.to.shared.u64 t, %1; cvt.u32.u64 %0, t; }" : "=r"(a) : "l"(p));
    return a;
}

// ---------------- kernel 1: normalize prototypes -> coalesced bf16 frags ----------------
__global__ void prep_kernel(const float* __restrict__ P) {
    int k = blockIdx.x;          // 64 blocks (one proto each)
    int t = threadIdx.x;         // 128 threads
    const float* row = P + k * PDIM;
    if (t == 0) g_Cnt[k] = 0;    // re-zeroed every replay before fused kernel

    float ss = 0.f;
    #pragma unroll
    for (int i = 0; i < 4; ++i) { float v = row[t + 128 * i]; ss += v * v; }
    __shared__ float red[4];
    #pragma unroll
    for (int o = 16; o > 0; o >>= 1) ss += __shfl_xor_sync(0xffffffffu, ss, o);
    if ((t & 31) == 0) red[t >> 5] = ss;
    __syncthreads();
    float norm = sqrtf(red[0] + red[1] + red[2] + red[3]);
    float inv = 1.f / fmaxf(norm, EPSN);

    int ks = t >> 2, q = t & 3;                    // 32 ksteps x 4 q
    int i0 = ks * 8 + q;                           // float2 index in row
    float2 fa = make_float2(row[2 * i0] * inv,       row[2 * i0 + 1] * inv);
    float2 fb = make_float2(row[2 * (i0 + 4)] * inv, row[2 * (i0 + 4) + 1] * inv);
    __nv_bfloat162 ha = __float22bfloat162_rn(fa);
    __nv_bfloat162 hb = __float22bfloat162_rn(fb);
    uint2 u;
    u.x = *reinterpret_cast<uint32_t*>(&ha);
    u.y = *reinterpret_cast<uint32_t*>(&hb);
    g_B[((k >> 3) * 32 + ks) * 32 + (k & 7) * 4 + q] = u;
}

// ---------------- kernel 2: FUSED, 2-way k-split (LDSM halved) ----------------
// 148 persistent CTAs x 512 threads, 3 __syncthreads per chunk.
// Warp w: rb=w>>3 (16 rows), kh=(w>>2)&1 (16 ksteps), pg=w&3 (16 protos=2 nblk).
// Each (rb,pg) pair of kh-warps computes half-K partial sims; kh=1 writes s_part,
// kh=0 merges + in-warp argmax(16 protos) -> cand[4pg][32]; t<32 reduces 4 pgs.
// Schedule per chunk k:
//   stage(k); S1; { prefetch(k+1) + mma(k) [+kh1 partial write] || accumulate(k-1) };
//   S2; kh0: merge+argmax -> cand(k); S3; t<32: reduce -> s_asg[k&1].
__global__ __launch_bounds__(512) void fused_kernel(const float* __restrict__ F) {
    extern __shared__ float acc[];                        // 64*512 f32 = 128 KB
    char*  s_A    = (char*)(acc + NPROTO * PDIM);         // 2 bufs x 32 rows x 1024B
    float* s_part = (float*)(s_A + 2 * CHUNK * 1024);     // [8 region][8 reg][32 lane] = 8 KB
    float* candV  = s_part + 2048;                        // [4][32]
    int*   candI  = (int*)(candV + 4 * 32);               // [4][32]
    unsigned char* s_asg = (unsigned char*)(candI + 4 * 32);  // [2][32], 8B-aligned

    int t = threadIdx.x;
    #pragma unroll
    for (int i = 0; i < NPROTO; ++i) acc[i * PDIM + t] = 0.f;

    int w = t >> 5, lane = t & 31;
    int rb = w >> 3;                      // row block: rows rb*16..+15
    int kh = (w >> 2) & 1;                // k half: ksteps kh*16..+15
    int pg = w & 3;                       // proto group: protos pg*16..+15
    int q = lane & 3, rg = lane >> 2;
    int rowB = rb * 16 + (lane & 15);     // ldmatrix row
    int halfSel = lane >> 4;              // 16B half selector
    uint32_t sA0 = smem_u32(s_A);
    float* pr = s_part + (rb * 4 + pg) * 256;   // partner exchange region

    // resident B fragments: 16 ks x 2 nblk (64 regs)
    uint2 Bf[16][2];
    #pragma unroll
    for (int i = 0; i < 16; ++i)
        #pragma unroll
        for (int nb = 0; nb < 2; ++nb)
            Bf[i][nb] = g_B[((pg * 2 + nb) * 32 + kh * 16 + i) * 32 + lane];

    // accumulate addressing: thread t -> row octet rh4, float4 column cp4
    int rh4 = t >> 7;                     // 0..3 -> rows rh4*8..rh4*8+7
    int cp4 = t & 127;                    // float4 column group
    int i16c = cp4 >> 1, inoffc = (cp4 & 1) * 8;
    float4* accp4 = reinterpret_cast<float4*>(acc);

    const float4* F4 = reinterpret_cast<const float4*>(F);
    int n = (NCHUNK - blockIdx.x + NACC - 1) / NACC;      // 42 or 43 chunks
    int cnt = 0;

    // prologue: prefetch + convert chunk 0
    uint2 u[8];
    {
        size_t cb = (size_t)blockIdx.x * (CHUNK * 128);
        #pragma unroll
        for (int j = 0; j < 8; ++j) {
            float4 v = F4[cb + j * 512 + t];
            __nv_bfloat162 h0 = __float22bfloat162_rn(make_float2(v.x, v.y));
            __nv_bfloat162 h1 = __float22bfloat162_rn(make_float2(v.z, v.w));
            u[j].x = *reinterpret_cast<uint32_t*>(&h0);
            u[j].y = *reinterpret_cast<uint32_t*>(&h1);
        }
    }
    __syncthreads();

    for (int k = 0; k < n; ++k) {
        // ---- stage chunk k into buf k&1 ----
        char* dst = s_A + (k & 1) * (CHUNK * 1024);
        #pragma unroll
        for (int j = 0; j < 8; ++j) {
            int idx = j * 512 + t;
            int row = idx >> 7;
            int c4  = idx & 127;
            int i16 = c4 >> 1;
            int sw  = (i16 & ~7) | ((i16 ^ row) & 7);
            *reinterpret_cast<uint2*>(dst + row * 1024 + sw * 16 + (c4 & 1) * 8) = u[j];
        }
        __syncthreads();   // S1: staging visible; s_asg[(k-1)&1] (from S3 region) visible

        // ---- prefetch + convert chunk k+1 ----
        if (k + 1 < n) {
            size_t cb = (size_t)(blockIdx.x + (k + 1) * NACC) * (CHUNK * 128);
            #pragma unroll
            for (int j = 0; j < 8; ++j) {
                float4 v = F4[cb + j * 512 + t];
                __nv_bfloat162 h0 = __float22bfloat162_rn(make_float2(v.x, v.y));
                __nv_bfloat162 h1 = __float22bfloat162_rn(make_float2(v.z, v.w));
                u[j].x = *reinterpret_cast<uint32_t*>(&h0);
                u[j].y = *reinterpret_cast<uint32_t*>(&h1);
            }
        }

        // ---- half-K MMA on chunk k: 16 rows x 16 protos x 16 ks ----
        float d[2][4];
        d[0][0] = d[0][1] = d[0][2] = d[0][3] = 0.f;
        d[1][0] = d[1][1] = d[1][2] = d[1][3] = 0.f;
        {
            uint32_t base = sA0 + (uint32_t)(k & 1) * (CHUNK * 1024);
            #pragma unroll
            for (int i = 0; i < 16; ++i) {
                int ks = kh * 16 + i;
                int i16 = ks * 2 + halfSel;
                int sw = (i16 & ~7) | ((i16 ^ rowB) & 7);
                uint32_t addr = base + rowB * 1024 + sw * 16;
                uint32_t a0, a1, a2, a3;
                asm volatile("ldmatrix.sync.aligned.m8n8.x4.shared.b16 {%0,%1,%2,%3}, [%4];"
                             : "=r"(a0), "=r"(a1), "=r"(a2), "=r"(a3) : "r"(addr));
                #pragma unroll
                for (int nb = 0; nb < 2; ++nb) {
                    asm volatile(
                        "mma.sync.aligned.m16n8k16.row.col.f32.bf16.bf16.f32 "
                        "{%0,%1,%2,%3}, {%4,%5,%6,%7}, {%8,%9}, {%0,%1,%2,%3};"
                        : "+f"(d[nb][0]), "+f"(d[nb][1]), "+f"(d[nb][2]), "+f"(d[nb][3])
                        : "r"(a0), "r"(a1), "r"(a2), "r"(a3),
                          "r"(Bf[i][nb].x), "r"(Bf[i][nb].y));
                }
            }
        }
        // kh=1 warps publish partials for partner merge
        if (kh == 1) {
            #pragma unroll
            for (int nb = 0; nb < 2; ++nb)
                #pragma unroll
                for (int j = 0; j < 4; ++j)
                    pr[(nb * 4 + j) * 32 + lane] = d[nb][j];
        }

        // ---- accumulate chunk k-1 (same phase: overlaps MMA across warps) ----
        if (k > 0) {
            int pb = (k - 1) & 1;
            const char* src = s_A + pb * (CHUNK * 1024);
            unsigned long long w0 = *reinterpret_cast<const unsigned long long*>(s_asg + pb * 32 + rh4 * 8);
            #pragma unroll
            for (int j = 0; j < 8; ++j) {
                int r = rh4 * 8 + j;
                int sw = (i16c & ~7) | ((i16c ^ r) & 7);
                uint2 hv = *reinterpret_cast<const uint2*>(src + r * 1024 + sw * 16 + inoffc);
                __nv_bfloat162 h0 = *reinterpret_cast<__nv_bfloat162*>(&hv.x);
                __nv_bfloat162 h1 = *reinterpret_cast<__nv_bfloat162*>(&hv.y);
                float2 f0 = __bfloat1622float2(h0);
                float2 f1 = __bfloat1622float2(h1);
                int a = (int)((w0 >> (8 * j)) & 255ull);
                float4 cur = accp4[a * (PDIM / 4) + cp4];
                cur.x += f0.x; cur.y += f0.y; cur.z += f1.x; cur.w += f1.y;
                accp4[a * (PDIM / 4) + cp4] = cur;
            }
            if (t < NPROTO) {
                #pragma unroll
                for (int jj = 0; jj < 4; ++jj) {
                    unsigned long long x = *reinterpret_cast<const unsigned long long*>(s_asg + pb * 32 + jj * 8);
                    #pragma unroll
                    for (int b = 0; b < 8; ++b)
                        cnt += (int)(((x >> (8 * b)) & 255ull) == (unsigned long long)t);
                }
            }
        }
        __syncthreads();   // S2: s_part complete; buf[(k-1)&1] free

        // ---- kh=0: merge partner partials + in-warp argmax over 16 protos ----
        if (kh == 0) {
            #pragma unroll
            for (int nb = 0; nb < 2; ++nb)
                #pragma unroll
                for (int j = 0; j < 4; ++j)
                    d[nb][j] += pr[(nb * 4 + j) * 32 + lane];
            #pragma unroll
            for (int half = 0; half < 2; ++half) {
                // protos pg*16 + nb*8 + 2q + j2, ascending (nb, j2) -> strict >
                float bv = d[0][half * 2];     int bi = pg * 16 + 2 * q;
                float v1 = d[0][half * 2 + 1];
                if (v1 > bv) { bv = v1; bi = pg * 16 + 2 * q + 1; }
                float v2 = d[1][half * 2];
                if (v2 > bv) { bv = v2; bi = pg * 16 + 8 + 2 * q; }
                float v3 = d[1][half * 2 + 1];
                if (v3 > bv) { bv = v3; bi = pg * 16 + 8 + 2 * q + 1; }
                #pragma unroll
                for (int off = 1; off <= 2; off <<= 1) {
                    float ov = __shfl_xor_sync(0xffffffffu, bv, off);
                    int   oi = __shfl_xor_sync(0xffffffffu, bi, off);
                    if (ov > bv || (ov == bv && oi < bi)) { bv = ov; bi = oi; }
                }
                if (q == 0) {
                    int row = rb * 16 + half * 8 + rg;
                    candV[pg * 32 + row] = bv;
                    candI[pg * 32 + row] = bi;
                }
            }
        }
        __syncthreads();   // S3: cand complete; s_part free for next chunk

        // ---- reduce candidates -> s_asg[k&1] (ascending pg, strict >) ----
        if (t < CHUNK) {
            float bv = candV[t]; int bi = candI[t];
            #pragma unroll
            for (int g = 1; g < 4; ++g) {
                float ov = candV[g * 32 + t];
                if (ov > bv) { bv = ov; bi = candI[g * 32 + t]; }
            }
            s_asg[(k & 1) * 32 + t] = (unsigned char)bi;
        }
        // next iteration's S1 orders this write before its consumers
    }

    __syncthreads();
    // epilogue: accumulate last chunk n-1
    {
        int pb = (n - 1) & 1;
        const char* src = s_A + pb * (CHUNK * 1024);
        unsigned long long w0 = *reinterpret_cast<const unsigned long long*>(s_asg + pb * 32 + rh4 * 8);
        #pragma unroll
        for (int j = 0; j < 8; ++j) {
            int r = rh4 * 8 + j;
            int sw = (i16c & ~7) | ((i16c ^ r) & 7);
            uint2 hv = *reinterpret_cast<const uint2*>(src + r * 1024 + sw * 16 + inoffc);
            __nv_bfloat162 h0 = *reinterpret_cast<__nv_bfloat162*>(&hv.x);
            __nv_bfloat162 h1 = *reinterpret_cast<__nv_bfloat162*>(&hv.y);
            float2 f0 = __bfloat1622float2(h0);
            float2 f1 = __bfloat1622float2(h1);
            int a = (int)((w0 >> (8 * j)) & 255ull);
            float4 cur = accp4[a * (PDIM / 4) + cp4];
            cur.x += f0.x; cur.y += f0.y; cur.z += f1.x; cur.w += f1.y;
            accp4[a * (PDIM / 4) + cp4] = cur;
        }
        if (t < NPROTO) {
            #pragma unroll
            for (int jj = 0; jj < 4; ++jj) {
                unsigned long long x = *reinterpret_cast<const unsigned long long*>(s_asg + pb * 32 + jj * 8);
                #pragma unroll
                for (int b = 0; b < 8; ++b)
                    cnt += (int)(((x >> (8 * b)) & 255ull) == (unsigned long long)t);
            }
        }
    }
    __syncthreads();

    // deterministic flush of this CTA's partial slice
    float* part = g_Partial + (size_t)blockIdx.x * (NPROTO * PDIM);
    #pragma unroll 4
    for (int k = 0; k < NPROTO; ++k) part[k * PDIM + t] = acc[k * PDIM + t];
    if (t < NPROTO) atomicAdd(&g_Cnt[t], cnt);   // int atomics: deterministic
}

// ---------------- kernel 3: reduce partials + EMA update ----------------
__global__ void finalize_kernel(const float* __restrict__ P, float* __restrict__ out) {
    int k = blockIdx.x >> 3;                          // 64 protos x 8 col-groups
    int t = ((blockIdx.x & 7) << 6) + threadIdx.x;    // 64 threads -> column
    float s = 0.f;
    #pragma unroll 8
    for (int b = 0; b < NACC; ++b)
        s += g_Partial[(size_t)b * (NPROTO * PDIM) + k * PDIM + t];
    int c = g_Cnt[k];
    float p = P[k * PDIM + t];
    float mean = s / fmaxf((float)c, 1.f);
    out[k * PDIM + t] = (c > 0) ? (0.9f * p + 0.1f * mean) : p;
}

// ---------------- launch ----------------
extern "C" void kernel_launch(void* const* d_in, const int* in_sizes, int n_in,
                              void* d_out, int out_size) {
    const float* F = (const float*)d_in[0];
    const float* P = (const float*)d_in[1];
    if (in_sizes[0] == NPROTO * PDIM) {     // robust to input order
        F = (const float*)d_in[1];
        P = (const float*)d_in[0];
    }

    prep_kernel<<<NPROTO, 128>>>(P);

    int smem = NPROTO * PDIM * (int)sizeof(float)   // 128 KB accumulator
             + 2 * CHUNK * 1024                     // 64 KB double-buffered staging
             + 2048 * (int)sizeof(float)            // 8 KB k-split partials
             + 4 * 32 * (int)sizeof(float)          // candV
             + 4 * 32 * (int)sizeof(int)            // candI
             + 64;                                  // s_asg[2][32]
    cudaFuncSetAttribute(fused_kernel, cudaFuncAttributeMaxDynamicSharedMemorySize, smem);
    fused_kernel<<<NACC, 512, smem>>>(F);

    finalize_kernel<<<NPROTO * 8, 64>>>(P, (float*)d_out);
}